// round 1
// baseline (speedup 1.0000x reference)
#include <cuda_runtime.h>

// Problem constants (fixed shapes from reference: B=8, K=4, N=131072)
#define TOT   4194304          // B*K*N
#define NDIM  131072           // N
#define CHUNK 4096             // elements per block
#define NBLK  1024             // TOT / CHUNK
#define NEG_PAD  (-1000.0f)
#define NEG_IDLE (-100000000.0f)

// Static device scratch (no allocations allowed)
__device__ unsigned char g_ms8[TOT];
__device__ unsigned char g_ma8[TOT];
__device__ unsigned int  g_partS[NBLK];
__device__ unsigned int  g_partA[NBLK];
__device__ int           g_kind;   // 0 = byte-per-element masks, 1 = word-per-element

// ---------------------------------------------------------------------------
// Phase 0: detect mask element width. bool masks serialized as u8 produce
// words with 0x01 bytes in positions 1..3 with overwhelming probability
// (density 0.3). int32/float32 masks produce only {0, 1, 0x3f800000}.
// ---------------------------------------------------------------------------
__global__ void detect_kernel(const unsigned int* __restrict__ ms) {
    __shared__ int notWord;
    if (threadIdx.x == 0) notWord = 0;
    __syncthreads();
    bool bad = false;
    for (int i = threadIdx.x; i < 2048; i += blockDim.x) {
        unsigned int w = ms[i];
        if (w != 0u && w != 1u && w != 0x3f800000u) bad = true;
    }
    if (bad) notWord = 1;   // benign race, all writers write 1
    __syncthreads();
    if (threadIdx.x == 0) g_kind = notWord ? 0 : 1;
}

// ---------------------------------------------------------------------------
// Phase 1: normalize masks to canonical u8 (0/1) scratch + per-chunk counts.
// 1024 blocks x 256 threads, 16 elements/thread.
// ---------------------------------------------------------------------------
__global__ void norm_count_kernel(const void* __restrict__ msRaw,
                                  const void* __restrict__ maRaw) {
    const int t  = threadIdx.x;
    const int i0 = blockIdx.x * CHUNK + t * 16;
    const int kind = g_kind;

    uint4 s4, a4;
    if (kind == 0) {
        s4 = ((const uint4*)msRaw)[i0 >> 4];
        a4 = ((const uint4*)maRaw)[i0 >> 4];
    } else {
        // one 32-bit word per element (int32 0/1 or float32 0.0/1.0):
        // nonzero word => true
        union { uint4 v; unsigned char b[16]; } us, ua;
        const uint4* ps = (const uint4*)msRaw + (i0 >> 2);
        const uint4* pa = (const uint4*)maRaw + (i0 >> 2);
#pragma unroll
        for (int q = 0; q < 4; ++q) {
            uint4 w = ps[q];
            us.b[q*4+0] = w.x ? 1 : 0; us.b[q*4+1] = w.y ? 1 : 0;
            us.b[q*4+2] = w.z ? 1 : 0; us.b[q*4+3] = w.w ? 1 : 0;
            uint4 v = pa[q];
            ua.b[q*4+0] = v.x ? 1 : 0; ua.b[q*4+1] = v.y ? 1 : 0;
            ua.b[q*4+2] = v.z ? 1 : 0; ua.b[q*4+3] = v.w ? 1 : 0;
        }
        s4 = us.v; a4 = ua.v;
    }
    ((uint4*)g_ms8)[i0 >> 4] = s4;
    ((uint4*)g_ma8)[i0 >> 4] = a4;

    // bytes are 0x00/0x01, so popcount of the word == byte sum
    unsigned int cS = __popc(s4.x) + __popc(s4.y) + __popc(s4.z) + __popc(s4.w);
    unsigned int cA = __popc(a4.x) + __popc(a4.y) + __popc(a4.z) + __popc(a4.w);
    unsigned int p = cS | (cA << 16);     // each <= 4096 block-wide: fits 16 bits
#pragma unroll
    for (int d = 16; d > 0; d >>= 1)
        p += __shfl_down_sync(0xffffffffu, p, d);

    __shared__ unsigned int sw[8];
    const int lane = t & 31, wid = t >> 5;
    if (lane == 0) sw[wid] = p;
    __syncthreads();
    if (t == 0) {
        unsigned int tot = 0;
#pragma unroll
        for (int w = 0; w < 8; ++w) tot += sw[w];
        g_partS[blockIdx.x] = tot & 0xFFFFu;
        g_partA[blockIdx.x] = tot >> 16;
    }
}

// ---------------------------------------------------------------------------
// Phase 2: exclusive scan of the 1024 chunk counts (single block, 1024 thr).
// Each thread touches only its own global element -> in-place is safe.
// ---------------------------------------------------------------------------
__global__ void scan_kernel() {
    const int t = threadIdx.x;
    const int lane = t & 31, wid = t >> 5;
    unsigned int s = g_partS[t], a = g_partA[t];
    unsigned int si = s, ai = a;
#pragma unroll
    for (int d = 1; d < 32; d <<= 1) {
        unsigned int vs = __shfl_up_sync(0xffffffffu, si, d);
        unsigned int va = __shfl_up_sync(0xffffffffu, ai, d);
        if (lane >= d) { si += vs; ai += va; }
    }
    __shared__ unsigned int wS[32], wA[32];
    if (lane == 31) { wS[wid] = si; wA[wid] = ai; }
    __syncthreads();
    if (wid == 0) {
        unsigned int ts = wS[lane], ta = wA[lane];
#pragma unroll
        for (int d = 1; d < 32; d <<= 1) {
            unsigned int vs = __shfl_up_sync(0xffffffffu, ts, d);
            unsigned int va = __shfl_up_sync(0xffffffffu, ta, d);
            if (lane >= d) { ts += vs; ta += va; }
        }
        wS[lane] = ts; wA[lane] = ta;
    }
    __syncthreads();
    unsigned int bS = wid ? wS[wid - 1] : 0u;
    unsigned int bA = wid ? wA[wid - 1] : 0u;
    g_partS[t] = bS + si - s;   // exclusive prefix
    g_partA[t] = bA + ai - a;
}

// ---------------------------------------------------------------------------
// Phase 3: gather + emit. 1024 blocks x 256 threads, 16 elements/thread,
// all stores as float4.
// Output layout (flattened tuple): [rgb_out 3*TOT][ls_out TOT][la_out TOT]
// ---------------------------------------------------------------------------
__global__ void output_kernel(const float* __restrict__ rgb,
                              const float* __restrict__ lsf,
                              const float* __restrict__ lar,
                              const float* __restrict__ idle_states,
                              float* __restrict__ out) {
    const int t    = threadIdx.x;
    const int blk  = blockIdx.x;
    const int base = blk * CHUNK;
    const int i0   = base + t * 16;

    union { uint4 v; unsigned char b[16]; } us, ua;
    us.v = ((const uint4*)g_ms8)[i0 >> 4];
    ua.v = ((const uint4*)g_ma8)[i0 >> 4];

    unsigned int cS = __popc(us.v.x) + __popc(us.v.y) + __popc(us.v.z) + __popc(us.v.w);
    unsigned int cA = __popc(ua.v.x) + __popc(ua.v.y) + __popc(ua.v.z) + __popc(ua.v.w);

    // packed 16+16 block-wide exclusive scan
    unsigned int packed = cS | (cA << 16);
    unsigned int inc = packed;
    const int lane = t & 31, wid = t >> 5;
#pragma unroll
    for (int d = 1; d < 32; d <<= 1) {
        unsigned int v = __shfl_up_sync(0xffffffffu, inc, d);
        if (lane >= d) inc += v;
    }
    __shared__ unsigned int wTot[8], wPre[8];
    if (lane == 31) wTot[wid] = inc;
    __syncthreads();
    if (t == 0) {
        unsigned int run = 0;
#pragma unroll
        for (int w = 0; w < 8; ++w) { wPre[w] = run; run += wTot[w]; }
    }
    __syncthreads();
    unsigned int exc  = wPre[wid] + inc - packed;
    unsigned int posS = (exc & 0xFFFFu) + g_partS[blk];
    unsigned int posA = (exc >> 16)     + g_partA[blk];

    // chunk (4096) divides N (131072) and base is chunk-aligned:
    // the whole block lies in one (b,k) row
    const int bk = base / NDIM;
    const float idle  = idle_states[bk];
    const float alive = 1.0f - idle;
    const float idn   = idle * NEG_IDLE;

    float* rgbOut = out;
    float* lsOut  = out + (size_t)3 * TOT;
    float* laOut  = out + (size_t)4 * TOT;

#pragma unroll
    for (int g = 0; g < 4; ++g) {
        float rv[12], lv[4], av[4];
#pragma unroll
        for (int j = 0; j < 4; ++j) {
            const int e = g * 4 + j;
            if (us.b[e]) {
                const float* rp = rgb + (size_t)posS * 3;
                rv[j*3+0] = rp[0] * alive;
                rv[j*3+1] = rp[1] * alive;
                rv[j*3+2] = rp[2] * alive;
                lv[j] = __ldg(lsf + posS) * alive + idn;
                ++posS;
            } else {
                rv[j*3+0] = 0.0f; rv[j*3+1] = 0.0f; rv[j*3+2] = 0.0f;
                lv[j] = NEG_PAD;
            }
            if (ua.b[e]) {
                av[j] = __ldg(lar + posA) * alive + idn;
                ++posA;
            } else {
                av[j] = NEG_PAD;
            }
        }
        const int i = i0 + g * 4;                 // i % 4 == 0
        float4* rdst = (float4*)(rgbOut + (size_t)i * 3);  // 48B-stride, 16B-aligned
        rdst[0] = make_float4(rv[0], rv[1], rv[2],  rv[3]);
        rdst[1] = make_float4(rv[4], rv[5], rv[6],  rv[7]);
        rdst[2] = make_float4(rv[8], rv[9], rv[10], rv[11]);
        *(float4*)(lsOut + i) = make_float4(lv[0], lv[1], lv[2], lv[3]);
        *(float4*)(laOut + i) = make_float4(av[0], av[1], av[2], av[3]);
    }
}

// ---------------------------------------------------------------------------
// Inputs (metadata order): rgb, logits_surface, logits_air, idle_states,
//                          mask_eval_surface, mask_eval_air
// ---------------------------------------------------------------------------
extern "C" void kernel_launch(void* const* d_in, const int* in_sizes, int n_in,
                              void* d_out, int out_size) {
    (void)in_sizes; (void)n_in; (void)out_size;
    const float* rgb  = (const float*)d_in[0];
    const float* lsf  = (const float*)d_in[1];
    const float* lar  = (const float*)d_in[2];
    const float* idle = (const float*)d_in[3];
    const void*  ms   = d_in[4];
    const void*  ma   = d_in[5];

    detect_kernel<<<1, 256>>>((const unsigned int*)ms);
    norm_count_kernel<<<NBLK, 256>>>(ms, ma);
    scan_kernel<<<1, 1024>>>();
    output_kernel<<<NBLK, 256>>>(rgb, lsf, lar, idle, (float*)d_out);
}

// round 4
// speedup vs baseline: 1.4469x; 1.4469x over previous
#include <cuda_runtime.h>

// Problem constants (fixed shapes: B=8, K=4, N=131072)
#define TOT    4194304          // B*K*N
#define NDIM   131072           // N
#define CHUNK  2048             // elements per block
#define NBLK   2048             // TOT / CHUNK
#define NEG_PAD  (-1000.0f)
#define NEG_IDLE (-100000000.0f)

// Static device scratch (no allocations allowed)
__device__ unsigned int g_partS[NBLK];
__device__ unsigned int g_partA[NBLK];
__device__ int          g_kind;   // 0 = byte-per-element masks, 1 = word-per-element

// ---------------------------------------------------------------------------
// Phase 0: detect mask element width. Byte masks (bool) produce words with
// 0x01 bytes in positions 1..3 with overwhelming probability (density 0.3);
// word masks (int32/float32) produce only {0, 1, 0x3f800000}.
// ---------------------------------------------------------------------------
__global__ void detect_kernel(const unsigned int* __restrict__ ms) {
    __shared__ int notWord;
    if (threadIdx.x == 0) notWord = 0;
    __syncthreads();
    bool bad = false;
    for (int i = threadIdx.x; i < 2048; i += blockDim.x) {
        unsigned int w = ms[i];
        if (w != 0u && w != 1u && w != 0x3f800000u) bad = true;
    }
    if (bad) notWord = 1;   // benign race, all writers write 1
    __syncthreads();
    if (threadIdx.x == 0) g_kind = notWord ? 0 : 1;
}

// bytes of w are 0/1 -> returns 4-bit mask (bit j = byte j)
__device__ __forceinline__ unsigned int nib01(unsigned int w) {
    return (w * 0x01020408u) >> 24;   // <= 15, no masking needed
}

// Build the 8-bit masks for elements [i0, i0+8) of both mask arrays.
__device__ __forceinline__ void load_masks8(const void* __restrict__ msRaw,
                                            const void* __restrict__ maRaw,
                                            int i0, int kind,
                                            unsigned int& mS, unsigned int& mA) {
    if (kind == 0) {
        uint2 s = ((const uint2*)msRaw)[i0 >> 3];
        uint2 a = ((const uint2*)maRaw)[i0 >> 3];
        mS = nib01(s.x) | (nib01(s.y) << 4);
        mA = nib01(a.x) | (nib01(a.y) << 4);
    } else {
        const uint4* ps = (const uint4*)msRaw + (i0 >> 2);
        const uint4* pa = (const uint4*)maRaw + (i0 >> 2);
        uint4 s0 = ps[0], s1 = ps[1];
        uint4 a0 = pa[0], a1 = pa[1];
        mS =  (s0.x ? 1u : 0u)       | (s0.y ? 2u : 0u)   | (s0.z ? 4u : 0u)   | (s0.w ? 8u : 0u)
           | (s1.x ? 16u : 0u)       | (s1.y ? 32u : 0u)  | (s1.z ? 64u : 0u)  | (s1.w ? 128u : 0u);
        mA =  (a0.x ? 1u : 0u)       | (a0.y ? 2u : 0u)   | (a0.z ? 4u : 0u)   | (a0.w ? 8u : 0u)
           | (a1.x ? 16u : 0u)       | (a1.y ? 32u : 0u)  | (a1.z ? 64u : 0u)  | (a1.w ? 128u : 0u);
    }
}

// ---------------------------------------------------------------------------
// Phase 1: per-chunk counts only (no scratch writes).
// 2048 blocks x 256 threads, 8 elements/thread.
// ---------------------------------------------------------------------------
__global__ void count_kernel(const void* __restrict__ msRaw,
                             const void* __restrict__ maRaw) {
    const int t  = threadIdx.x;
    const int i0 = blockIdx.x * CHUNK + t * 8;
    const int kind = g_kind;

    unsigned int mS, mA;
    load_masks8(msRaw, maRaw, i0, kind, mS, mA);

    // pack both counts: each block total <= 2048, fits 16 bits
    unsigned int p = __popc(mS) | (__popc(mA) << 16);
#pragma unroll
    for (int d = 16; d > 0; d >>= 1)
        p += __shfl_down_sync(0xffffffffu, p, d);

    __shared__ unsigned int sw[8];
    const int lane = t & 31, wid = t >> 5;
    if (lane == 0) sw[wid] = p;
    __syncthreads();
    if (t == 0) {
        unsigned int tot = 0;
#pragma unroll
        for (int w = 0; w < 8; ++w) tot += sw[w];
        g_partS[blockIdx.x] = tot & 0xFFFFu;
        g_partA[blockIdx.x] = tot >> 16;
    }
}

// ---------------------------------------------------------------------------
// Phase 2: exclusive scan of the 2048 chunk counts (single block, 1024 thr,
// 2 entries per thread). Each thread only touches its own entries -> in-place.
// ---------------------------------------------------------------------------
__global__ void scan_kernel() {
    const int t = threadIdx.x;
    const int lane = t & 31, wid = t >> 5;
    unsigned int s0 = g_partS[2*t], s1 = g_partS[2*t+1];
    unsigned int a0 = g_partA[2*t], a1 = g_partA[2*t+1];
    unsigned int s = s0 + s1, a = a0 + a1;
    unsigned int si = s, ai = a;
#pragma unroll
    for (int d = 1; d < 32; d <<= 1) {
        unsigned int vs = __shfl_up_sync(0xffffffffu, si, d);
        unsigned int va = __shfl_up_sync(0xffffffffu, ai, d);
        if (lane >= d) { si += vs; ai += va; }
    }
    __shared__ unsigned int wS[32], wA[32];
    if (lane == 31) { wS[wid] = si; wA[wid] = ai; }
    __syncthreads();
    if (wid == 0) {
        unsigned int ts = wS[lane], ta = wA[lane];
#pragma unroll
        for (int d = 1; d < 32; d <<= 1) {
            unsigned int vs = __shfl_up_sync(0xffffffffu, ts, d);
            unsigned int va = __shfl_up_sync(0xffffffffu, ta, d);
            if (lane >= d) { ts += vs; ta += va; }
        }
        wS[lane] = ts; wA[lane] = ta;
    }
    __syncthreads();
    unsigned int excS = (wid ? wS[wid - 1] : 0u) + si - s;   // exclusive prefix
    unsigned int excA = (wid ? wA[wid - 1] : 0u) + ai - a;
    g_partS[2*t]   = excS;
    g_partS[2*t+1] = excS + s0;
    g_partA[2*t]   = excA;
    g_partA[2*t+1] = excA + a0;
}

// ---------------------------------------------------------------------------
// Phase 3: gather + emit. 2048 blocks x 256 threads, 8 elements/thread.
// Bitmask-derived positions -> all gather loads independent (high MLP).
// Output layout (flattened tuple): [rgb_out 3*TOT][ls_out TOT][la_out TOT]
// ---------------------------------------------------------------------------
__global__ void __launch_bounds__(256)
output_kernel(const void* __restrict__ msRaw,
              const void* __restrict__ maRaw,
              const float* __restrict__ rgb,
              const float* __restrict__ lsf,
              const float* __restrict__ lar,
              const float* __restrict__ idle_states,
              float* __restrict__ out) {
    const int t    = threadIdx.x;
    const int blk  = blockIdx.x;
    const int base = blk * CHUNK;
    const int i0   = base + t * 8;
    const int kind = g_kind;

    unsigned int mS, mA;
    load_masks8(msRaw, maRaw, i0, kind, mS, mA);

    // packed 16+16 block-wide exclusive scan (block totals <= 2048 each)
    unsigned int packed = __popc(mS) | (__popc(mA) << 16);
    unsigned int inc = packed;
    const int lane = t & 31, wid = t >> 5;
#pragma unroll
    for (int d = 1; d < 32; d <<= 1) {
        unsigned int v = __shfl_up_sync(0xffffffffu, inc, d);
        if (lane >= d) inc += v;
    }
    __shared__ unsigned int wTot[8], wPre[8];
    if (lane == 31) wTot[wid] = inc;
    __syncthreads();
    if (t == 0) {
        unsigned int run = 0;
#pragma unroll
        for (int w = 0; w < 8; ++w) { wPre[w] = run; run += wTot[w]; }
    }
    __syncthreads();
    const unsigned int exc   = wPre[wid] + inc - packed;
    const unsigned int posS0 = (exc & 0xFFFFu) + g_partS[blk];
    const unsigned int posA0 = (exc >> 16)     + g_partA[blk];

    // whole block lies in one (b,k) row (CHUNK divides NDIM, base aligned)
    const int bk = base / NDIM;
    const float idle  = idle_states[bk];
    const float alive = 1.0f - idle;
    const float idn   = idle * NEG_IDLE;

    float* rgbOut = out;
    float* lsOut  = out + (size_t)3 * TOT;
    float* laOut  = out + (size_t)4 * TOT;

#pragma unroll
    for (int g = 0; g < 2; ++g) {
        float rv[12], lv[4], av[4];
#pragma unroll
        for (int j = 0; j < 4; ++j) {
            const int e = g * 4 + j;
            const unsigned int below = (1u << e) - 1u;
            if ((mS >> e) & 1u) {
                const unsigned int p = posS0 + __popc(mS & below);
                const float* rp = rgb + (size_t)p * 3;
                rv[3*j+0] = __ldg(rp + 0) * alive;
                rv[3*j+1] = __ldg(rp + 1) * alive;
                rv[3*j+2] = __ldg(rp + 2) * alive;
                lv[j] = __ldg(lsf + p) * alive + idn;
            } else {
                rv[3*j+0] = 0.0f; rv[3*j+1] = 0.0f; rv[3*j+2] = 0.0f;
                lv[j] = NEG_PAD;
            }
            if ((mA >> e) & 1u) {
                const unsigned int p = posA0 + __popc(mA & below);
                av[j] = __ldg(lar + p) * alive + idn;
            } else {
                av[j] = NEG_PAD;
            }
        }
        const int i = i0 + g * 4;                     // i % 4 == 0
        float4* rdst = (float4*)(rgbOut + (size_t)i * 3);  // 48B stride, 16B aligned
        rdst[0] = make_float4(rv[0], rv[1], rv[2],  rv[3]);
        rdst[1] = make_float4(rv[4], rv[5], rv[6],  rv[7]);
        rdst[2] = make_float4(rv[8], rv[9], rv[10], rv[11]);
        *(float4*)(lsOut + i) = make_float4(lv[0], lv[1], lv[2], lv[3]);
        *(float4*)(laOut + i) = make_float4(av[0], av[1], av[2], av[3]);
    }
}

// ---------------------------------------------------------------------------
// Inputs (metadata order): rgb, logits_surface, logits_air, idle_states,
//                          mask_eval_surface, mask_eval_air
// ---------------------------------------------------------------------------
extern "C" void kernel_launch(void* const* d_in, const int* in_sizes, int n_in,
                              void* d_out, int out_size) {
    (void)in_sizes; (void)n_in; (void)out_size;
    const float* rgb  = (const float*)d_in[0];
    const float* lsf  = (const float*)d_in[1];
    const float* lar  = (const float*)d_in[2];
    const float* idle = (const float*)d_in[3];
    const void*  ms   = d_in[4];
    const void*  ma   = d_in[5];

    detect_kernel<<<1, 256>>>((const unsigned int*)ms);
    count_kernel<<<NBLK, 256>>>(ms, ma);
    scan_kernel<<<1, 1024>>>();
    output_kernel<<<NBLK, 256>>>(ms, ma, rgb, lsf, lar, idle, (float*)d_out);
}